// round 3
// baseline (speedup 1.0000x reference)
#include <cuda_runtime.h>

// DenseTNT postprocess: per-batch greedy NMS over 4096 goal candidates.
// k-th pick = argmax score among candidates not suppressed (d2 < 4.0) by
// already-picked goals. Tie-break: equal score -> lower original index,
// encoded in 64-bit key = (ordered_float(score) << 32) | (~idx).
// Warp argmax via REDUX; winner (x,y) rides along with the warp partial.

#define B_       128
#define N_       4096
#define MODES_   6
#define THRESH2_ 4.0f
#define TPB_     512
#define PER_     8           // candidates per thread, contiguous chunk
#define NW_      (TPB_ / 32) // 16 warps

struct __align__(16) Part { unsigned long long key; float x, y; };

__global__ __launch_bounds__(TPB_, 1)
void densetnt_nms_kernel(const float* __restrict__ scores,   // [B, N]
                         const float* __restrict__ trajs,    // [B, 60, N]
                         const float* __restrict__ goals,    // [B, 2, N]
                         float* __restrict__ out)            // [B,6,30,2] ++ [B,6]
{
    const int b    = blockIdx.x;
    const int t    = threadIdx.x;
    const int w    = t >> 5;
    const int lane = t & 31;

    __shared__ Part red[2][NW_];                 // parity double-buffer
    __shared__ unsigned long long win_s[MODES_];
    __shared__ int   sel_s[MODES_];
    __shared__ float ssc_s[MODES_];

    const float* sc = scores + (size_t)b * N_     + (size_t)t * PER_;
    const float* gx = goals  + (size_t)b * 2 * N_ + (size_t)t * PER_;
    const float* gy = gx + N_;

    // Vectorized loads: per-thread contiguous chunk of 8 candidates.
    float4 s0 = ((const float4*)sc)[0], s1 = ((const float4*)sc)[1];
    float4 a0 = ((const float4*)gx)[0], a1 = ((const float4*)gx)[1];
    float4 c0 = ((const float4*)gy)[0], c1 = ((const float4*)gy)[1];

    float x[PER_]  = {a0.x, a0.y, a0.z, a0.w, a1.x, a1.y, a1.z, a1.w};
    float y[PER_]  = {c0.x, c0.y, c0.z, c0.w, c1.x, c1.y, c1.z, c1.w};
    float sv[PER_] = {s0.x, s0.y, s0.z, s0.w, s1.x, s1.y, s1.z, s1.w};

    unsigned long long key[PER_];
#pragma unroll
    for (int j = 0; j < PER_; j++) {
        unsigned u  = __float_as_uint(sv[j]);
        unsigned os = (u & 0x80000000u) ? ~u : (u | 0x80000000u); // order-preserving
        key[j] = ((unsigned long long)os << 32)
               | (unsigned long long)(0xFFFFFFFFu - (unsigned)(t * PER_ + j));
    }

    for (int m = 0; m < MODES_; m++) {
        // local argmax over 8 candidates (killed -> key==0)
        unsigned long long bkey = key[0];
        int bj = 0;
#pragma unroll
        for (int j = 1; j < PER_; j++)
            if (key[j] > bkey) { bkey = key[j]; bj = j; }

        // warp argmax via two REDUX ops (hi = score bits, lo = ~idx)
        unsigned hi = (unsigned)(bkey >> 32);
        unsigned lo = (unsigned)bkey;
        unsigned wh = __reduce_max_sync(0xFFFFFFFFu, hi);
        unsigned ml = (hi == wh) ? lo : 0u;
        unsigned wl = __reduce_max_sync(0xFFFFFFFFu, ml);
        unsigned long long wkey = ((unsigned long long)wh << 32) | wl;

        // exactly one lane publishes the warp partial (keys are unique)
        bool owner = (wkey == 0ull) ? (lane == 0)
                                    : (hi == wh && lo == wl);
        if (owner) {
            Part p; p.key = wkey; p.x = x[bj]; p.y = y[bj];
            red[m & 1][w] = p;
        }
        __syncthreads();   // only barrier this round

        // every thread reduces the 16 warp partials (broadcast LDS.128)
        unsigned long long win = 0ull;
        float wxv = 0.f, wyv = 0.f;
#pragma unroll
        for (int ww = 0; ww < NW_; ww++) {
            Part p = red[m & 1][ww];
            if (p.key > win) { win = p.key; wxv = p.x; wyv = p.y; }
        }
        if (t == 0) win_s[m] = win;

        if (win != 0ull) {
#pragma unroll
            for (int j = 0; j < PER_; j++) {
                float dx = x[j] - wxv;
                float dy = y[j] - wyv;
                if (dx * dx + dy * dy < THRESH2_) key[j] = 0ull;
            }
        }
        // no barrier here: next round writes the other parity buffer; the
        // round-(m+1) barrier bounds warp skew to one round.
    }
    __syncthreads();   // win_s[] complete

    // decode selections (empty slot -> round-0 winner = global top-1)
    if (t < MODES_) {
        unsigned long long wv = win_s[t];
        if (wv == 0ull) wv = win_s[0];
        sel_s[t] = (int)(0xFFFFFFFFu - (unsigned)(wv & 0xFFFFFFFFull));
        unsigned os = (unsigned)(wv >> 32);
        unsigned su = (os & 0x80000000u) ? (os & 0x7FFFFFFFu) : ~os;
        ssc_s[t] = __uint_as_float(su);
    }
    __syncthreads();

    // gather: out trajs [B,6,30,2] then scores [B,6]
    const float* tb = trajs + (size_t)b * 60 * N_;
    float* ob = out + (size_t)b * MODES_ * 60;
    for (int e = t; e < MODES_ * 60; e += TPB_) {
        int m = e / 60;
        int k = e - m * 60;
        ob[e] = __ldg(tb + (size_t)k * N_ + sel_s[m]);
    }
    if (t < MODES_) {
        out[(size_t)B_ * MODES_ * 60 + (size_t)b * MODES_ + t] = ssc_s[t];
    }
}

extern "C" void kernel_launch(void* const* d_in, const int* in_sizes, int n_in,
                              void* d_out, int out_size)
{
    const float* goals_scores = (const float*)d_in[0];  // [128, 4096]
    const float* traj_preds   = (const float*)d_in[1];  // [128, 60, 4096]
    const float* pred_goals   = (const float*)d_in[2];  // [128, 2, 4096]
    float* out = (float*)d_out;

    densetnt_nms_kernel<<<B_, TPB_>>>(goals_scores, traj_preds, pred_goals, out);
}